// round 5
// baseline (speedup 1.0000x reference)
#include <cuda_runtime.h>
#include <cstdint>

// Shapes (fixed for this problem)
#define B_   64
#define N_   2048
#define A_   512
#define RNN_ 1024
#define DW_  1024
#define DS_  1024
#define NCHUNK 16
#define NPER   (N_ / NCHUNK)   // 128

// k1 split-K GEMM config
#define KSPLIT 16
#define KCH    (RNN_ / KSPLIT)   // 64

// Scratch (device globals: no allocation allowed)
__device__ float g_pk1[KSPLIT * B_ * A_];       // 2 MB   (k1 partials)
__device__ float g_hword[B_ * A_];              // 128 KB
__device__ float g_scores[B_ * N_];             // 512 KB (raw scores)
__device__ float g_stats[2 * B_];               // [b]=row max, [B_+b]=1/sum
__device__ float g_partial[B_ * NCHUNK * DW_];  // 4 MB

__device__ __forceinline__ float tanh_fast(float x) {
    float r;
    asm("tanh.approx.f32 %0, %1;" : "=f"(r) : "f"(x));
    return r;
}

__device__ __forceinline__ float warp_sum(float v) {
    #pragma unroll
    for (int o = 16; o; o >>= 1) v += __shfl_xor_sync(0xffffffffu, v, o);
    return v;
}

// ---------------------------------------------------------------------------
// K1: split-K tiled GEMM. pk1[ks][b][a] = sum_{k in chunk ks} h[b,k] * W[a,k]
// grid = (16, 16), block = 256.
// ---------------------------------------------------------------------------
__global__ void k1_gemm(const float* __restrict__ h,
                        const float* __restrict__ W,
                        float* __restrict__ pk1) {
    const int a0 = blockIdx.x * 32;
    const int k0 = blockIdx.y * KCH;

    __shared__ float sH[64][KCH + 4];
    __shared__ float sW[32][KCH + 4];

    for (int idx = threadIdx.x; idx < 64 * (KCH / 4); idx += 256) {
        const int row = idx >> 4, kk = idx & 15;
        float4 v = *(const float4*)(h + (size_t)row * RNN_ + k0 + kk * 4);
        *(float4*)(&sH[row][kk * 4]) = v;
    }
    for (int idx = threadIdx.x; idx < 32 * (KCH / 4); idx += 256) {
        const int row = idx >> 4, kk = idx & 15;
        float4 v = *(const float4*)(W + (size_t)(a0 + row) * RNN_ + k0 + kk * 4);
        *(float4*)(&sW[row][kk * 4]) = v;
    }
    __syncthreads();

    const int b  = threadIdx.x & 63;
    const int ag = threadIdx.x >> 6;

    float acc[8] = {0.f, 0.f, 0.f, 0.f, 0.f, 0.f, 0.f, 0.f};
    #pragma unroll 8
    for (int k4 = 0; k4 < KCH / 4; k4++) {
        const float4 hv = *(const float4*)(&sH[b][k4 * 4]);
        #pragma unroll
        for (int j = 0; j < 8; j++) {
            const float4 wv = *(const float4*)(&sW[ag * 8 + j][k4 * 4]);
            acc[j] += hv.x * wv.x + hv.y * wv.y + hv.z * wv.z + hv.w * wv.w;
        }
    }

    float* dst = pk1 + ((size_t)blockIdx.y * B_ + b) * A_ + a0 + ag * 8;
    #pragma unroll
    for (int j = 0; j < 8; j++) dst[j] = acc[j];
}

// ---------------------------------------------------------------------------
// K1r: hw[b][a] = bias[a] + sum_ks pk1[ks][b][a].
// ---------------------------------------------------------------------------
__global__ void k1_reduce(const float* __restrict__ pk1,
                          const float* __restrict__ bias,
                          float* __restrict__ hw) {
    const int idx = blockIdx.x * 256 + threadIdx.x;
    const int c = idx & 127;
    float4 acc = ((const float4*)bias)[c];
    const int b = idx >> 7;
    #pragma unroll
    for (int ks = 0; ks < KSPLIT; ks++) {
        float4 v = ((const float4*)pk1)[((size_t)ks * B_ + b) * (A_ / 4) + c];
        acc.x += v.x; acc.y += v.y; acc.z += v.z; acc.w += v.w;
    }
    ((float4*)hw)[idx] = acc;
}

// ---------------------------------------------------------------------------
// K2: scores[b,n] = sum_a tanh(p[b,n,a] + hw[b,a]) * walpha[a]
// grid = (N_/32, B_), block = 256 (8 warps, 4 n per warp).
// Per chunk i: 4 rows' loads issue back-to-back (MLP 4, no serializing
// reduction in between); 4 independent accumulators, epilogue reduction.
// ---------------------------------------------------------------------------
__global__ void k2_scores(const float* __restrict__ p,
                          const float* __restrict__ hw,
                          const float* __restrict__ walpha,
                          float* __restrict__ scores) {
    const int b = blockIdx.y;
    const int warp = threadIdx.x >> 5, lane = threadIdx.x & 31;
    const int n0 = blockIdx.x * 32 + warp * 4;

    float4 hv[4], wv[4];
    #pragma unroll
    for (int i = 0; i < 4; i++) {
        hv[i] = __ldg((const float4*)(hw + (size_t)b * A_) + lane + 32 * i);
        wv[i] = __ldg((const float4*)walpha + lane + 32 * i);
    }

    const float4* pr = (const float4*)(p + ((size_t)b * N_ + n0) * A_);
    float acc[4] = {0.f, 0.f, 0.f, 0.f};

    #pragma unroll
    for (int i = 0; i < 4; i++) {
        float4 v[4];
        #pragma unroll
        for (int nn = 0; nn < 4; nn++)
            v[nn] = __ldcs(pr + (size_t)nn * (A_ / 4) + lane + 32 * i);
        #pragma unroll
        for (int nn = 0; nn < 4; nn++) {
            acc[nn] += tanh_fast(v[nn].x + hv[i].x) * wv[i].x;
            acc[nn] += tanh_fast(v[nn].y + hv[i].y) * wv[i].y;
            acc[nn] += tanh_fast(v[nn].z + hv[i].z) * wv[i].z;
            acc[nn] += tanh_fast(v[nn].w + hv[i].w) * wv[i].w;
        }
    }

    #pragma unroll
    for (int nn = 0; nn < 4; nn++) {
        float r = warp_sum(acc[nn]);
        if (lane == 0) scores[(size_t)b * N_ + n0 + nn] = r;
    }
}

// ---------------------------------------------------------------------------
// K3: per-row softmax STATS only: stats[b]=max, stats[B_+b]=1/sum(exp(s-m)).
// grid = B_, block = 1024 (2 elements/thread). k4 applies exp inline.
// ---------------------------------------------------------------------------
__global__ void k3_stats(const float* __restrict__ scores,
                         float* __restrict__ stats) {
    const int b = blockIdx.x;
    const float* row = scores + (size_t)b * N_;
    const int t = threadIdx.x;
    const int warp = t >> 5, lane = t & 31;
    __shared__ float red[32];

    const float s0 = row[t];
    const float s1 = row[t + 1024];

    // max reduce
    float m = fmaxf(s0, s1);
    #pragma unroll
    for (int o = 16; o; o >>= 1) m = fmaxf(m, __shfl_xor_sync(0xffffffffu, m, o));
    if (lane == 0) red[warp] = m;
    __syncthreads();
    if (warp == 0) {
        m = red[lane];
        #pragma unroll
        for (int o = 16; o; o >>= 1) m = fmaxf(m, __shfl_xor_sync(0xffffffffu, m, o));
        if (lane == 0) red[0] = m;
    }
    __syncthreads();
    m = red[0];

    // sum of exp
    float sum = __expf(s0 - m) + __expf(s1 - m);
    sum = warp_sum(sum);
    __syncthreads();
    if (lane == 0) red[warp] = sum;
    __syncthreads();
    if (warp == 0) {
        sum = red[lane];
        sum = warp_sum(sum);
        if (lane == 0) {
            stats[b] = m;
            stats[B_ + b] = 1.0f / sum;
        }
    }
}

// ---------------------------------------------------------------------------
// K4: partial[b,c,d] = sum_{n in chunk c} softmax_w[b,n] * swf[b,n,d]
// grid = (NCHUNK, B_), block = 256, 4 CTAs/SM. Weights computed inline from
// raw scores + stats. Explicit 8-deep register load batching for MLP=8.
// ---------------------------------------------------------------------------
__global__ void __launch_bounds__(256, 4)
k4_pool(const float* __restrict__ swf,
        const float* __restrict__ scores,
        const float* __restrict__ stats,
        float* __restrict__ partial) {
    const int b = blockIdx.y, c = blockIdx.x;
    __shared__ float sw[NPER];
    {
        const float m   = stats[b];
        const float inv = stats[B_ + b];
        for (int i = threadIdx.x; i < NPER; i += blockDim.x)
            sw[i] = __expf(scores[(size_t)b * N_ + c * NPER + i] - m) * inv;
    }
    __syncthreads();

    const float4* x = (const float4*)(swf + ((size_t)b * N_ + (size_t)c * NPER) * DW_);
    const int t = threadIdx.x;
    float4 acc = make_float4(0.f, 0.f, 0.f, 0.f);

    #pragma unroll 2
    for (int nb = 0; nb < NPER / 8; nb++) {
        float4 v[8];
        float  w[8];
        #pragma unroll
        for (int j = 0; j < 8; j++)
            v[j] = __ldcs(x + (size_t)(nb * 8 + j) * (DW_ / 4) + t);
        #pragma unroll
        for (int j = 0; j < 8; j++)
            w[j] = sw[nb * 8 + j];
        #pragma unroll
        for (int j = 0; j < 8; j++) {
            acc.x += w[j] * v[j].x; acc.y += w[j] * v[j].y;
            acc.z += w[j] * v[j].z; acc.w += w[j] * v[j].w;
        }
    }
    ((float4*)partial)[((size_t)b * NCHUNK + c) * (DW_ / 4) + t] = acc;
}

// ---------------------------------------------------------------------------
// K5: out[b] = concat(senti_feats[b], sum_c partial[b,c,:]). grid = B_, 256.
// ---------------------------------------------------------------------------
__global__ void k5_finish(const float* __restrict__ senti,
                          const float* __restrict__ partial,
                          float* __restrict__ out) {
    const int b = blockIdx.x, t = threadIdx.x;
    float4* orow = (float4*)(out + (size_t)b * (DS_ + DW_));
    orow[t] = ((const float4*)(senti + (size_t)b * DS_))[t];
    float4 acc = make_float4(0.f, 0.f, 0.f, 0.f);
    #pragma unroll
    for (int c = 0; c < NCHUNK; c++) {
        float4 v = __ldg(((const float4*)partial) + ((size_t)b * NCHUNK + c) * (DW_ / 4) + t);
        acc.x += v.x; acc.y += v.y; acc.z += v.z; acc.w += v.w;
    }
    orow[DS_ / 4 + t] = acc;
}

// ---------------------------------------------------------------------------
extern "C" void kernel_launch(void* const* d_in, const int* in_sizes, int n_in,
                              void* d_out, int out_size) {
    const float* h      = (const float*)d_in[0];  // [B, RNN]
    const float* senti  = (const float*)d_in[1];  // [B, DS]
    const float* swf    = (const float*)d_in[2];  // [B, N, DW]
    const float* p      = (const float*)d_in[3];  // [B, N, A]
    const float* W      = (const float*)d_in[4];  // [A, RNN]
    const float* bvec   = (const float*)d_in[5];  // [A]
    const float* walpha = (const float*)d_in[6];  // [A]
    // d_in[7] = b_alpha: softmax-invariant, ignored.

    float* pk1;     cudaGetSymbolAddress((void**)&pk1,     g_pk1);
    float* hw;      cudaGetSymbolAddress((void**)&hw,      g_hword);
    float* scores;  cudaGetSymbolAddress((void**)&scores,  g_scores);
    float* stats;   cudaGetSymbolAddress((void**)&stats,   g_stats);
    float* partial; cudaGetSymbolAddress((void**)&partial, g_partial);

    k1_gemm  <<<dim3(A_ / 32, KSPLIT), 256>>>(h, W, pk1);
    k1_reduce<<<(B_ * A_ / 4) / 256, 256>>>(pk1, bvec, hw);
    k2_scores<<<dim3(N_ / 32, B_), 256>>>(p, hw, walpha, scores);
    k3_stats <<<B_, 1024>>>(scores, stats);
    k4_pool  <<<dim3(NCHUNK, B_), 256>>>(swf, scores, stats, partial);
    k5_finish<<<B_, 256>>>(senti, partial, (float*)d_out);
}